// round 7
// baseline (speedup 1.0000x reference)
#include <cuda_runtime.h>

// out = cumprod_j( cos(w_j) * cos(x @ W_pre^T + b_pre) ) @ W_post^T + b_post
//
// Analytic reduction of the quantum layer:
//   z_j   = cos(q_weights_j) * cos(angle_j)
//   <Z_i> = prod_{j<=i} z_j            (CNOT chain = prefix-XOR)
//
// 2 rows/block, 512 threads, grid=128 (1 block/SM, single wave).
//   - weights (W_pre row + W_post slice) register-cached, reused by both rows
//   - TWO barriers only: [x staged] and [angles ready]
//   - prefix scan computed redundantly per warp; broadcast via warp-private
//     smem + __syncwarp (no third __syncthreads)
//   - dual accumulators per row in phase 1 (shorter FFMA chains, more ILP)

#define NQ   16
#define DIN  1024
#define DOUT 1024
#define B    256

__global__ __launch_bounds__(512, 1)
void quantum_projector_kernel(const float* __restrict__ x,
                              const float* __restrict__ W_pre,
                              const float* __restrict__ b_pre,
                              const float* __restrict__ q_weights,
                              const float* __restrict__ W_post,
                              const float* __restrict__ b_post,
                              float* __restrict__ out)
{
    __shared__ float4 sx0[DIN / 4];      // 4 KB: row r0
    __shared__ float4 sx1[DIN / 4];      // 4 KB: row r1
    __shared__ float  s_angle[2 * NQ];   // [row][qubit]
    __shared__ float  s_wz[16][32];      // warp-private scan broadcast slots

    const int r0   = blockIdx.x * 2;
    const int r1   = r0 + 1;
    const int tid  = threadIdx.x;
    const int warp = tid >> 5;           // 16 warps = 16 qubits
    const int lane = tid & 31;

    // ---- Stage both x rows into smem (512 threads, one float4 each) ----
    {
        const float4* __restrict__ x4 = reinterpret_cast<const float4*>(x);
        if (tid < 256) sx0[tid]       = x4[r0 * (DIN / 4) + tid];
        else           sx1[tid - 256] = x4[r1 * (DIN / 4) + (tid - 256)];
    }

    // ---- Weight prefetch into registers (shared by both rows) ----
    const float4* __restrict__ w4 = reinterpret_cast<const float4*>(W_pre + warp * DIN);
    float4 wv[8];
#pragma unroll
    for (int i = 0; i < 8; i++)
        wv[i] = w4[lane + 32 * i];

    // Thread t covers output cols o0=2t, o1=2t+1 (same cols for both rows).
    const float4* __restrict__ Wp4 = reinterpret_cast<const float4*>(W_post);
    float4 wreg[8];
#pragma unroll
    for (int i = 0; i < 8; i++)
        wreg[i] = Wp4[8 * tid + i];
    const float2 bp = reinterpret_cast<const float2*>(b_post)[tid];

    __syncthreads();   // barrier 1: x staged

    // ---- Phase 1: both rows' angle[warp]; 2 accumulators/row for ILP ----
    {
        float a0e = 0.f, a0o = 0.f, a1e = 0.f, a1o = 0.f;
#pragma unroll
        for (int i = 0; i < 4; i++) {
            const int ke = lane + 32 * (2 * i);
            const int ko = lane + 32 * (2 * i + 1);
            float4 xe0 = sx0[ke], xo0 = sx0[ko];
            float4 xe1 = sx1[ke], xo1 = sx1[ko];
            const float4 we = wv[2 * i], wo = wv[2 * i + 1];
            a0e += xe0.x * we.x + xe0.y * we.y + xe0.z * we.z + xe0.w * we.w;
            a0o += xo0.x * wo.x + xo0.y * wo.y + xo0.z * wo.z + xo0.w * wo.w;
            a1e += xe1.x * we.x + xe1.y * we.y + xe1.z * we.z + xe1.w * we.w;
            a1o += xo1.x * wo.x + xo1.y * wo.y + xo1.z * wo.z + xo1.w * wo.w;
        }
        float acc0 = a0e + a0o;
        float acc1 = a1e + a1o;
#pragma unroll
        for (int off = 16; off >= 1; off >>= 1) {
            acc0 += __shfl_xor_sync(0xffffffffu, acc0, off);
            acc1 += __shfl_xor_sync(0xffffffffu, acc1, off);
        }
        if (lane == 0) {
            const float b = b_pre[warp];
            s_angle[warp]      = acc0 + b;
            s_angle[NQ + warp] = acc1 + b;
        }
    }
    __syncthreads();   // barrier 2: angles ready

    // ---- Phase 2: EVERY warp computes the dual-row prefix scan ----
    // lanes 0..15 -> row0, lanes 16..31 -> row1 (segmented shfl_up scan),
    // then broadcast within the warp through its private smem slot.
    float z0[NQ], z1[NQ];
    {
        const int q   = lane & 15;
        const int seg = lane >> 4;
        float v = __cosf(q_weights[q]) * __cosf(s_angle[seg * NQ + q]);
#pragma unroll
        for (int off = 1; off <= 8; off <<= 1) {
            float t = __shfl_up_sync(0xffffffffu, v, off);
            if (q >= off) v *= t;    // segment boundary: q < off blocks carry-in
        }
        s_wz[warp][lane] = v;
        __syncwarp();
#pragma unroll
        for (int j = 0; j < NQ; j++) {
            z0[j] = s_wz[warp][j];
            z1[j] = s_wz[warp][16 + j];
        }
    }

    // ---- Phase 3: 2 cols x 2 rows per thread from register W_post ----
    float d00 = 0.f, d01 = 0.f, d10 = 0.f, d11 = 0.f;
#pragma unroll
    for (int i = 0; i < 4; i++) {
        const float4 wa = wreg[i];       // col o0, qubits 4i..4i+3
        const float4 wb = wreg[4 + i];   // col o1
        d00 += z0[4*i] * wa.x + z0[4*i+1] * wa.y + z0[4*i+2] * wa.z + z0[4*i+3] * wa.w;
        d01 += z0[4*i] * wb.x + z0[4*i+1] * wb.y + z0[4*i+2] * wb.z + z0[4*i+3] * wb.w;
        d10 += z1[4*i] * wa.x + z1[4*i+1] * wa.y + z1[4*i+2] * wa.z + z1[4*i+3] * wa.w;
        d11 += z1[4*i] * wb.x + z1[4*i+1] * wb.y + z1[4*i+2] * wb.z + z1[4*i+3] * wb.w;
    }

    float2* __restrict__ o0 = reinterpret_cast<float2*>(out + r0 * DOUT);
    float2* __restrict__ o1 = reinterpret_cast<float2*>(out + r1 * DOUT);
    o0[tid] = make_float2(bp.x + d00, bp.y + d01);
    o1[tid] = make_float2(bp.x + d10, bp.y + d11);
}

extern "C" void kernel_launch(void* const* d_in, const int* in_sizes, int n_in,
                              void* d_out, int out_size)
{
    const float* x         = (const float*)d_in[0];   // [256, 1024]
    const float* W_pre     = (const float*)d_in[1];   // [16, 1024]
    const float* b_pre     = (const float*)d_in[2];   // [16]
    const float* q_weights = (const float*)d_in[3];   // [16]
    const float* W_post    = (const float*)d_in[4];   // [1024, 16]
    const float* b_post    = (const float*)d_in[5];   // [1024]
    float* out             = (float*)d_out;           // [256, 1024]

    quantum_projector_kernel<<<B / 2, 512>>>(x, W_pre, b_pre, q_weights,
                                             W_post, b_post, out);
}

// round 8
// speedup vs baseline: 1.8607x; 1.8607x over previous
#include <cuda_runtime.h>

// out = cumprod_j( cos(w_j) * cos(x @ W_pre^T + b_pre) ) @ W_post^T + b_post
//
// Analytic reduction of the quantum layer:
//   z_j   = cos(q_weights_j) * cos(angle_j)
//   <Z_i> = prod_{j<=i} z_j            (CNOT chain = prefix-XOR)
//
// Block = (row pair, column half): grid=256 x 512 thr, 2 blocks/SM resident
// (launch_bounds(512,2) caps regs at 64) so memory stalls of one block are
// covered by the other. W_post half-slice register-cached and reused across
// the 2 rows; W_pre loaded in-loop (short lifetimes); zq read via LDS.128.

#define NQ   16
#define DIN  1024
#define DOUT 1024
#define B    256

__global__ __launch_bounds__(512, 2)
void quantum_projector_kernel(const float* __restrict__ x,
                              const float* __restrict__ W_pre,
                              const float* __restrict__ b_pre,
                              const float* __restrict__ q_weights,
                              const float* __restrict__ W_post,
                              const float* __restrict__ b_post,
                              float* __restrict__ out)
{
    __shared__ float4 sx0[DIN / 4];      // 4 KB: row r0
    __shared__ float4 sx1[DIN / 4];      // 4 KB: row r1
    __shared__ float  s_angle[2 * NQ];   // [row][qubit]
    __shared__ float4 s_zq4[8];          // [row][4] = 2 x 16 floats

    const int bx   = blockIdx.x;
    const int pair = bx >> 1;            // which row pair
    const int half = bx & 1;             // which 512-column half
    const int r0   = pair * 2;
    const int r1   = r0 + 1;
    const int tid  = threadIdx.x;
    const int warp = tid >> 5;           // 16 warps = 16 qubits
    const int lane = tid & 31;

    // ---- Stage both x rows into smem (512 threads, one float4 each) ----
    {
        const float4* __restrict__ x4 = reinterpret_cast<const float4*>(x);
        if (tid < 256) sx0[tid]       = x4[r0 * (DIN / 4) + tid];
        else           sx1[tid - 256] = x4[r1 * (DIN / 4) + (tid - 256)];
    }

    // ---- Prefetch this thread's W_post column (shared by both rows) ----
    const int col = half * 512 + tid;
    const float4* __restrict__ Wp4 = reinterpret_cast<const float4*>(W_post);
    float4 wreg[4];
#pragma unroll
    for (int i = 0; i < 4; i++)
        wreg[i] = Wp4[col * 4 + i];
    const float bp = b_post[col];

    __syncthreads();   // barrier 1: x staged

    // ---- Phase 1: both rows' angle[warp]; W_pre loaded in-loop ----
    {
        const float4* __restrict__ w4 = reinterpret_cast<const float4*>(W_pre + warp * DIN);
        float a0e = 0.f, a0o = 0.f, a1e = 0.f, a1o = 0.f;
#pragma unroll
        for (int i = 0; i < 4; i++) {
            const int ke = lane + 64 * i;
            const int ko = ke + 32;
            const float4 we = w4[ke], wo = w4[ko];
            const float4 xe0 = sx0[ke], xo0 = sx0[ko];
            const float4 xe1 = sx1[ke], xo1 = sx1[ko];
            a0e += xe0.x * we.x + xe0.y * we.y + xe0.z * we.z + xe0.w * we.w;
            a0o += xo0.x * wo.x + xo0.y * wo.y + xo0.z * wo.z + xo0.w * wo.w;
            a1e += xe1.x * we.x + xe1.y * we.y + xe1.z * we.z + xe1.w * we.w;
            a1o += xo1.x * wo.x + xo1.y * wo.y + xo1.z * wo.z + xo1.w * wo.w;
        }
        float acc0 = a0e + a0o;
        float acc1 = a1e + a1o;
#pragma unroll
        for (int off = 16; off >= 1; off >>= 1) {
            acc0 += __shfl_xor_sync(0xffffffffu, acc0, off);
            acc1 += __shfl_xor_sync(0xffffffffu, acc1, off);
        }
        if (lane == 0) {
            const float b = b_pre[warp];
            s_angle[warp]      = acc0 + b;
            s_angle[NQ + warp] = acc1 + b;
        }
    }
    __syncthreads();   // barrier 2: angles ready

    // ---- Phase 2: warp 0 does BOTH rows' prefix products ----
    // lanes 0..15 -> row0, lanes 16..31 -> row1 (segmented shfl_up scan)
    if (warp == 0) {
        const int q   = lane & 15;
        const int seg = lane >> 4;
        float v = __cosf(q_weights[q]) * __cosf(s_angle[seg * NQ + q]);
#pragma unroll
        for (int off = 1; off <= 8; off <<= 1) {
            float t = __shfl_up_sync(0xffffffffu, v, off);
            if (q >= off) v *= t;   // segment boundary: q < off blocks carry-in
        }
        reinterpret_cast<float*>(s_zq4)[seg * NQ + q] = v;
    }
    __syncthreads();   // barrier 3: zq ready

    // ---- Phase 3: one column x 2 rows per thread; zq via LDS.128 ----
    float d0 = bp, d1 = bp;
#pragma unroll
    for (int i = 0; i < 4; i++) {
        const float4 za = s_zq4[i];       // row0 qubits 4i..4i+3 (broadcast LDS)
        const float4 zb = s_zq4[4 + i];   // row1
        const float4 w  = wreg[i];
        d0 += za.x * w.x + za.y * w.y + za.z * w.z + za.w * w.w;
        d1 += zb.x * w.x + zb.y * w.y + zb.z * w.z + zb.w * w.w;
    }

    out[r0 * DOUT + col] = d0;
    out[r1 * DOUT + col] = d1;
}

extern "C" void kernel_launch(void* const* d_in, const int* in_sizes, int n_in,
                              void* d_out, int out_size)
{
    const float* x         = (const float*)d_in[0];   // [256, 1024]
    const float* W_pre     = (const float*)d_in[1];   // [16, 1024]
    const float* b_pre     = (const float*)d_in[2];   // [16]
    const float* q_weights = (const float*)d_in[3];   // [16]
    const float* W_post    = (const float*)d_in[4];   // [1024, 16]
    const float* b_post    = (const float*)d_in[5];   // [1024]
    float* out             = (float*)d_out;           // [256, 1024]

    quantum_projector_kernel<<<B, 512>>>(x, W_pre, b_pre, q_weights,
                                         W_post, b_post, out);
}

// round 9
// speedup vs baseline: 1.9225x; 1.0332x over previous
#include <cuda_runtime.h>

// out = cumprod_j( cos(w_j) * cos(x @ W_pre^T + b_pre) ) @ W_post^T + b_post
//
// Analytic reduction of the quantum layer:
//   z_j   = cos(q_weights_j) * cos(angle_j)
//   <Z_i> = prod_{j<=i} z_j            (CNOT chain = prefix-XOR)
//
// Block = (row pair, column half): grid=256 x 512 thr, 2 blocks/SM.
//   - ALL global loads (x stage, W_pre row, W_post cols, b_post) issued
//     before barrier 1 -> single latency exposure, max MLP
//   - phase 1: pure LDS+FFMA dual-row dot, dual accumulators
//   - phase 2: every warp computes the dual-row segmented prefix scan
//     redundantly; broadcast via warp-private smem + __syncwarp
//     (no third __syncthreads)
//   - phase 3: 1 col x 2 rows per thread from register W_post + LDS.128 zq

#define NQ   16
#define DIN  1024
#define DOUT 1024
#define B    256

__global__ __launch_bounds__(512, 2)
void quantum_projector_kernel(const float* __restrict__ x,
                              const float* __restrict__ W_pre,
                              const float* __restrict__ b_pre,
                              const float* __restrict__ q_weights,
                              const float* __restrict__ W_post,
                              const float* __restrict__ b_post,
                              float* __restrict__ out)
{
    __shared__ float4 sx0[DIN / 4];      // 4 KB: row r0
    __shared__ float4 sx1[DIN / 4];      // 4 KB: row r1
    __shared__ float  s_angle[2 * NQ];   // [row][qubit]
    __shared__ float4 s_wz[16][8];       // warp-private scan slots: [warp][row*4+i]

    const int bx   = blockIdx.x;
    const int pair = bx >> 1;            // which row pair
    const int half = bx & 1;             // which 512-column half
    const int r0   = pair * 2;
    const int r1   = r0 + 1;
    const int tid  = threadIdx.x;
    const int warp = tid >> 5;           // 16 warps = 16 qubits
    const int lane = tid & 31;

    // ---- Stage both x rows into smem (512 threads, one float4 each) ----
    {
        const float4* __restrict__ x4 = reinterpret_cast<const float4*>(x);
        if (tid < 256) sx0[tid]       = x4[r0 * (DIN / 4) + tid];
        else           sx1[tid - 256] = x4[r1 * (DIN / 4) + (tid - 256)];
    }

    // ---- Prefetch W_pre row for this warp's qubit (registers) ----
    const float4* __restrict__ w4 = reinterpret_cast<const float4*>(W_pre + warp * DIN);
    float4 wv[8];
#pragma unroll
    for (int i = 0; i < 8; i++)
        wv[i] = w4[lane + 32 * i];

    // ---- Prefetch this thread's W_post column (shared by both rows) ----
    const int col = half * 512 + tid;
    const float4* __restrict__ Wp4 = reinterpret_cast<const float4*>(W_post);
    float4 wreg[4];
#pragma unroll
    for (int i = 0; i < 4; i++)
        wreg[i] = Wp4[col * 4 + i];
    const float bp = b_post[col];

    __syncthreads();   // barrier 1: x staged (all LDG latency amortized here)

    // ---- Phase 1: both rows' angle[warp]; pure LDS+FFMA ----
    {
        float a0e = 0.f, a0o = 0.f, a1e = 0.f, a1o = 0.f;
#pragma unroll
        for (int i = 0; i < 4; i++) {
            const int ke = lane + 64 * i;
            const int ko = ke + 32;
            const float4 we = wv[2 * i], wo = wv[2 * i + 1];
            const float4 xe0 = sx0[ke], xo0 = sx0[ko];
            const float4 xe1 = sx1[ke], xo1 = sx1[ko];
            a0e += xe0.x * we.x + xe0.y * we.y + xe0.z * we.z + xe0.w * we.w;
            a0o += xo0.x * wo.x + xo0.y * wo.y + xo0.z * wo.z + xo0.w * wo.w;
            a1e += xe1.x * we.x + xe1.y * we.y + xe1.z * we.z + xe1.w * we.w;
            a1o += xo1.x * wo.x + xo1.y * wo.y + xo1.z * wo.z + xo1.w * wo.w;
        }
        float acc0 = a0e + a0o;
        float acc1 = a1e + a1o;
#pragma unroll
        for (int off = 16; off >= 1; off >>= 1) {
            acc0 += __shfl_xor_sync(0xffffffffu, acc0, off);
            acc1 += __shfl_xor_sync(0xffffffffu, acc1, off);
        }
        if (lane == 0) {
            const float b = b_pre[warp];
            s_angle[warp]      = acc0 + b;
            s_angle[NQ + warp] = acc1 + b;
        }
    }
    __syncthreads();   // barrier 2: angles ready

    // ---- Phase 2: EVERY warp computes the dual-row prefix scan ----
    // lanes 0..15 -> row0, lanes 16..31 -> row1 (segmented shfl_up scan),
    // broadcast within the warp through its private smem slot (no block barrier).
    {
        const int q   = lane & 15;
        const int seg = lane >> 4;
        float v = __cosf(q_weights[q]) * __cosf(s_angle[seg * NQ + q]);
#pragma unroll
        for (int off = 1; off <= 8; off <<= 1) {
            float t = __shfl_up_sync(0xffffffffu, v, off);
            if (q >= off) v *= t;   // segment boundary: q < off blocks carry-in
        }
        reinterpret_cast<float*>(s_wz[warp])[lane] = v;
        __syncwarp();
    }

    // ---- Phase 3: one column x 2 rows per thread; zq via LDS.128 ----
    float d0 = bp, d1 = bp;
#pragma unroll
    for (int i = 0; i < 4; i++) {
        const float4 za = s_wz[warp][i];       // row0 qubits 4i..4i+3
        const float4 zb = s_wz[warp][4 + i];   // row1
        const float4 w  = wreg[i];
        d0 += za.x * w.x + za.y * w.y + za.z * w.z + za.w * w.w;
        d1 += zb.x * w.x + zb.y * w.y + zb.z * w.z + zb.w * w.w;
    }

    out[r0 * DOUT + col] = d0;
    out[r1 * DOUT + col] = d1;
}

extern "C" void kernel_launch(void* const* d_in, const int* in_sizes, int n_in,
                              void* d_out, int out_size)
{
    const float* x         = (const float*)d_in[0];   // [256, 1024]
    const float* W_pre     = (const float*)d_in[1];   // [16, 1024]
    const float* b_pre     = (const float*)d_in[2];   // [16]
    const float* q_weights = (const float*)d_in[3];   // [16]
    const float* W_post    = (const float*)d_in[4];   // [1024, 16]
    const float* b_post    = (const float*)d_in[5];   // [1024]
    float* out             = (float*)d_out;           // [256, 1024]

    quantum_projector_kernel<<<B, 512>>>(x, W_pre, b_pre, q_weights,
                                         W_post, b_post, out);
}